// round 3
// baseline (speedup 1.0000x reference)
#include <cuda_runtime.h>
#include <cstdint>

typedef unsigned long long u64;

// ---------- f32x2 packed math (sm_103a) ----------
__device__ __forceinline__ u64 pk2(float lo, float hi) {
    u64 r;
    asm("mov.b64 %0, {%1, %2};" : "=l"(r) : "r"(__float_as_uint(lo)), "r"(__float_as_uint(hi)));
    return r;
}
__device__ __forceinline__ void upk2(u64 v, float& lo, float& hi) {
    unsigned a, b;
    asm("mov.b64 {%0, %1}, %2;" : "=r"(a), "=r"(b) : "l"(v));
    lo = __uint_as_float(a); hi = __uint_as_float(b);
}
__device__ __forceinline__ u64 fma2(u64 a, u64 b, u64 c) {
    u64 d;
    asm("fma.rn.f32x2 %0, %1, %2, %3;" : "=l"(d) : "l"(a), "l"(b), "l"(c));
    return d;
}
__device__ __forceinline__ u64 add2(u64 a, u64 b) {
    u64 d;
    asm("add.rn.f32x2 %0, %1, %2;" : "=l"(d) : "l"(a), "l"(b));
    return d;
}
__device__ __forceinline__ float hadd2(u64 v) {
    float lo, hi; upk2(v, lo, hi); return lo + hi;
}
__device__ __forceinline__ u64 relu2(u64 v) {
    float lo, hi; upk2(v, lo, hi);
    return pk2(fmaxf(lo, 0.f), fmaxf(hi, 0.f));
}

// ---------- per-point precomputed first-layer projections ----------
__device__ float g_A0[1024 * 32];
__device__ float g_B0[1024 * 32];
__device__ float g_A1[1024 * 32];
__device__ float g_B1[1024 * 32];

__global__ void ppf_pre(const float* __restrict__ feat,
                        const float* __restrict__ w0, const float* __restrict__ b0,
                        const float* __restrict__ w1, const float* __restrict__ b1) {
    int t = blockIdx.x * blockDim.x + threadIdx.x;   // 32768 threads
    int i = t >> 5, c = t & 31;
    const float* f = feat + i * 40;
    float a0 = b0[c], bo0 = 0.f, a1 = b1[c], bo1 = 0.f;
#pragma unroll 8
    for (int k = 0; k < 40; k++) {
        float fv = f[k];
        a0  = fmaf(fv, w0[k * 32 + c],        a0);
        bo0 = fmaf(fv, w0[(k + 40) * 32 + c], bo0);
        a1  = fmaf(fv, w1[k * 32 + c],        a1);
        bo1 = fmaf(fv, w1[(k + 40) * 32 + c], bo1);
    }
    g_A0[i * 32 + c] = a0;
    g_B0[i * 32 + c] = bo0;
    g_A1[i * 32 + c] = a1;
    g_B1[i * 32 + c] = bo1;
}

// ---------- shared memory layout (units: floats) ----------
// Transposed weights: u64 element [t][n] = (w[2t][n], w[2t+1][n]); stored as 2 floats.
#define O_W1T    0        // [2][32] u64  = 128 fl
#define O_W0T    128      // 128 fl
#define O_L0W2T  256      // [16][32] u64 = 1024 fl
#define O_L1W1T  1280     // 1024
#define O_L1W2T  2304     // 1024
#define O_L2W0T  3328     // [16][16] u64 = 512
#define O_L2W1T  3840     // 512
#define O_L2W2T  4352     // [8][16] u64 = 256
#define O_FWT    4608     // [8][66] u64 = 1056
#define O_L0B2   5664     // 32
#define O_L1B1   5696     // 32
#define O_L1B2   5728     // 32
#define O_L2B0   5760     // 16
#define O_L2B1   5776     // 16
#define O_L2B2   5792     // 16
#define O_FB     5808     // 66 (pad to 5888)
#define O_OUT    5888     // 8 warps * 64 rows * 66
#define SMEM_FLOATS (5888 + 8 * 64 * 66)
#define SMEM_BYTES  (SMEM_FLOATS * 4)

// stage transposed+k-paired weights: dst u64[k/2][N]
__device__ __forceinline__ void stageT(float* dst, const float* __restrict__ src,
                                       int K, int N, int tid) {
    int half = K / 2;
    for (int idx = tid; idx < half * N; idx += 256) {
        int t = idx / N, n = idx % N;
        dst[2 * idx]     = src[(2 * t) * N + n];
        dst[2 * idx + 1] = src[(2 * t + 1) * N + n];
    }
}

// GEMM core: acc_n (k-split u64 partial sums) for NN outputs starting at n0.
// Weights at s+woff are [KH][N] u64, loaded as ulonglong2 (LDS.128).
template<int KH, int NN>
__device__ __forceinline__ void gemmT(const float* __restrict__ s, int woff, int N, int n0,
                                      const u64* __restrict__ xp0, const u64* __restrict__ xp1,
                                      u64* __restrict__ a0, u64* __restrict__ a1) {
#pragma unroll
    for (int n = 0; n < NN; n++) { a0[n] = 0ull; a1[n] = 0ull; }
#pragma unroll
    for (int t = 0; t < KH; t++) {
        u64 x0 = xp0[t], x1 = xp1[t];
        const ulonglong2* w = (const ulonglong2*)(s + woff + (t * N + n0) * 2);
#pragma unroll
        for (int n2 = 0; n2 < NN / 2; n2++) {
            ulonglong2 wv = w[n2];
            a0[2 * n2]     = fma2(x0, wv.x, a0[2 * n2]);
            a1[2 * n2]     = fma2(x1, wv.x, a1[2 * n2]);
            a0[2 * n2 + 1] = fma2(x0, wv.y, a0[2 * n2 + 1]);
            a1[2 * n2 + 1] = fma2(x1, wv.y, a1[2 * n2 + 1]);
        }
    }
}

// horizontal-reduce NN k-split accs into NN/2 packed outputs, + bias, optional relu
template<int NN, bool RELU>
__device__ __forceinline__ void redT(const u64* __restrict__ a0, const u64* __restrict__ a1,
                                     const float* __restrict__ s, int boff,
                                     u64* __restrict__ o0, u64* __restrict__ o1) {
    const u64* bb = (const u64*)(s + boff);
#pragma unroll
    for (int m = 0; m < NN / 2; m++) {
        u64 bp = bb[m];
        u64 v0 = add2(pk2(hadd2(a0[2 * m]), hadd2(a0[2 * m + 1])), bp);
        u64 v1 = add2(pk2(hadd2(a1[2 * m]), hadd2(a1[2 * m + 1])), bp);
        if (RELU) { v0 = relu2(v0); v1 = relu2(v1); }
        o0[m] = v0; o1[m] = v1;
    }
}

__global__ __launch_bounds__(256, 1)
void ppf_main(const float* __restrict__ pc, const float* __restrict__ nrm,
              const float* __restrict__ dist,
              const float* __restrict__ fc0w, const float* __restrict__ fc1w,
              const float* __restrict__ l0w2, const float* __restrict__ l0b2,
              const float* __restrict__ l1w1, const float* __restrict__ l1b1,
              const float* __restrict__ l1w2, const float* __restrict__ l1b2,
              const float* __restrict__ l2w0, const float* __restrict__ l2b0,
              const float* __restrict__ l2w1, const float* __restrict__ l2b1,
              const float* __restrict__ l2w2, const float* __restrict__ l2b2,
              const float* __restrict__ fw, const float* __restrict__ fb,
              float* __restrict__ out) {
    extern __shared__ float s[];
    const int tid = threadIdx.x;
    const int lane = tid & 31;
    const int warp = tid >> 5;

    // ---- weight staging (transposed, k-paired) ----
    stageT(s + O_W1T,   fc1w + 80 * 32, 4,  32, tid);
    stageT(s + O_W0T,   fc0w + 80 * 32, 4,  32, tid);
    stageT(s + O_L0W2T, l0w2, 32, 32, tid);
    stageT(s + O_L1W1T, l1w1, 32, 32, tid);
    stageT(s + O_L1W2T, l1w2, 32, 32, tid);
    stageT(s + O_L2W0T, l2w0, 32, 16, tid);
    stageT(s + O_L2W1T, l2w1, 32, 16, tid);
    stageT(s + O_L2W2T, l2w2, 16, 16, tid);
    stageT(s + O_FWT,   fw,   16, 66, tid);
    for (int t = tid; t < 32; t += 256) s[O_L0B2 + t] = l0b2[t];
    for (int t = tid; t < 32; t += 256) s[O_L1B1 + t] = l1b1[t];
    for (int t = tid; t < 32; t += 256) s[O_L1B2 + t] = l1b2[t];
    for (int t = tid; t < 16; t += 256) s[O_L2B0 + t] = l2b0[t];
    for (int t = tid; t < 16; t += 256) s[O_L2B1 + t] = l2b1[t];
    for (int t = tid; t < 16; t += 256) s[O_L2B2 + t] = l2b2[t];
    for (int t = tid; t < 66; t += 256) s[O_FB + t]   = fb[t];
    __syncthreads();

    // 2 pairs per thread: (i, jb+lane), (i, jb+lane+32)
    const int i = blockIdx.x >> 1;
    const int jb = ((blockIdx.x & 1) << 9) + (warp << 6);
    const int j0 = jb + lane;
    const int j1 = j0 + 32;

    // ---- PPF features ----
    float pcix = pc[3 * i], pciy = pc[3 * i + 1], pciz = pc[3 * i + 2];
    float nix = nrm[3 * i], niy = nrm[3 * i + 1], niz = nrm[3 * i + 2];
    u64 pp0[2], pp1[2];
#pragma unroll
    for (int pr = 0; pr < 2; pr++) {
        int j = pr ? j1 : j0;
        float pcjx = pc[3 * j], pcjy = pc[3 * j + 1], pcjz = pc[3 * j + 2];
        float njx = nrm[3 * j], njy = nrm[3 * j + 1], njz = nrm[3 * j + 2];
        float d = dist[(i << 10) + j];
        float inv = 1.0f / (d + 1e-7f);
        float xx0 = pcix - pcjx, xx1 = pciy - pcjy, xx2 = pciz - pcjz;
        float q0 = (nix * xx0 + niy * xx1 + niz * xx2) * inv;
        float q1 = (njx * xx0 + njy * xx1 + njz * xx2) * inv;
        float q2 = nix * njx + niy * njy + niz * njz;
        if (pr == 0) { pp0[0] = pk2(q0, q1); pp0[1] = pk2(q2, d); }
        else         { pp1[0] = pk2(q0, q1); pp1[1] = pk2(q2, d); }
    }

    // ---- layer0: h = relu(A1[i] + B1[j] + ppf@w1p)  (A1 has b1 folded) ----
    const u64* A1  = (const u64*)(g_A1 + (i << 5));
    const u64* B1a = (const u64*)(g_B1 + (j0 << 5));
    const u64* B1b = (const u64*)(g_B1 + (j1 << 5));
    u64 h0[16], h1[16];
#pragma unroll
    for (int c = 0; c < 4; c++) {
        u64 a0[8], a1[8];
        gemmT<2, 8>(s, O_W1T, 32, c * 8, pp0, pp1, a0, a1);
#pragma unroll
        for (int m = 0; m < 4; m++) {
            u64 ab = A1[c * 4 + m];
            u64 v0 = add2(pk2(hadd2(a0[2 * m]), hadd2(a0[2 * m + 1])), add2(ab, B1a[c * 4 + m]));
            u64 v1 = add2(pk2(hadd2(a1[2 * m]), hadd2(a1[2 * m + 1])), add2(ab, B1b[c * 4 + m]));
            h0[c * 4 + m] = relu2(v0);
            h1[c * 4 + m] = relu2(v1);
        }
    }

    // ---- x = h @ l0_fc2 + b2 ----
    u64 x0[16], x1[16];
#pragma unroll
    for (int c = 0; c < 4; c++) {
        u64 a0[8], a1[8];
        gemmT<16, 8>(s, O_L0W2T, 32, c * 8, h0, h1, a0, a1);
        redT<8, false>(a0, a1, s, O_L0B2 + c * 8, &x0[c * 4], &x1[c * 4]);
    }
    // ---- += residual: A0[i] + B0[j] + ppf@w0p  (A0 has b0 folded) ----
    {
        const u64* A0  = (const u64*)(g_A0 + (i << 5));
        const u64* B0a = (const u64*)(g_B0 + (j0 << 5));
        const u64* B0b = (const u64*)(g_B0 + (j1 << 5));
#pragma unroll
        for (int c = 0; c < 4; c++) {
            u64 a0[8], a1[8];
            gemmT<2, 8>(s, O_W0T, 32, c * 8, pp0, pp1, a0, a1);
#pragma unroll
            for (int m = 0; m < 4; m++) {
                u64 ab = A0[c * 4 + m];
                u64 v0 = add2(pk2(hadd2(a0[2 * m]), hadd2(a0[2 * m + 1])), add2(ab, B0a[c * 4 + m]));
                u64 v1 = add2(pk2(hadd2(a1[2 * m]), hadd2(a1[2 * m + 1])), add2(ab, B0b[c * 4 + m]));
                x0[c * 4 + m] = add2(x0[c * 4 + m], v0);
                x1[c * 4 + m] = add2(x1[c * 4 + m], v1);
            }
        }
    }

    // ---- layer1: x += relu(x@W1+b1)@W2 + b2 ----
#pragma unroll
    for (int c = 0; c < 4; c++) {
        u64 a0[8], a1[8];
        gemmT<16, 8>(s, O_L1W1T, 32, c * 8, x0, x1, a0, a1);
        redT<8, true>(a0, a1, s, O_L1B1 + c * 8, &h0[c * 4], &h1[c * 4]);
    }
#pragma unroll
    for (int c = 0; c < 4; c++) {
        u64 a0[8], a1[8];
        gemmT<16, 8>(s, O_L1W2T, 32, c * 8, h0, h1, a0, a1);
        u64 t0[4], t1[4];
        redT<8, false>(a0, a1, s, O_L1B2 + c * 8, t0, t1);
#pragma unroll
        for (int m = 0; m < 4; m++) {
            x0[c * 4 + m] = add2(x0[c * 4 + m], t0[m]);
            x1[c * 4 + m] = add2(x1[c * 4 + m], t1[m]);
        }
    }

    // ---- layer2 ----
    u64 hh0[8], hh1[8];
#pragma unroll
    for (int c = 0; c < 2; c++) {
        u64 a0[8], a1[8];
        gemmT<16, 8>(s, O_L2W1T, 16, c * 8, x0, x1, a0, a1);
        redT<8, true>(a0, a1, s, O_L2B1 + c * 8, &hh0[c * 4], &hh1[c * 4]);
    }
    u64 r0[8], r1[8];
#pragma unroll
    for (int c = 0; c < 2; c++) {
        u64 a0[8], a1[8];
        gemmT<16, 8>(s, O_L2W0T, 16, c * 8, x0, x1, a0, a1);
        redT<8, false>(a0, a1, s, O_L2B0 + c * 8, &r0[c * 4], &r1[c * 4]);
    }
    u64 x30[8], x31[8];
#pragma unroll
    for (int c = 0; c < 2; c++) {
        u64 a0[8], a1[8];
        gemmT<8, 8>(s, O_L2W2T, 16, c * 8, hh0, hh1, a0, a1);
        u64 t0[4], t1[4];
        redT<8, false>(a0, a1, s, O_L2B2 + c * 8, t0, t1);
#pragma unroll
        for (int m = 0; m < 4; m++) {
            x30[c * 4 + m] = add2(t0[m], r0[c * 4 + m]);
            x31[c * 4 + m] = add2(t1[m], r1[c * 4 + m]);
        }
    }

    // ---- final 16 -> 66, chunks of 22; reduce straight into staging smem ----
    {
        float* wbase = s + O_OUT + warp * (64 * 66);
        u64* wb0 = (u64*)(wbase + lane * 66);
        u64* wb1 = (u64*)(wbase + (lane + 32) * 66);
#pragma unroll
        for (int c = 0; c < 3; c++) {
            u64 a0[22], a1[22];
            gemmT<8, 22>(s, O_FWT, 66, c * 22, x30, x31, a0, a1);
            const u64* fbp = (const u64*)(s + O_FB) + c * 11;
#pragma unroll
            for (int m = 0; m < 11; m++) {
                u64 bp = fbp[m];
                wb0[c * 11 + m] = add2(pk2(hadd2(a0[2 * m]), hadd2(a0[2 * m + 1])), bp);
                wb1[c * 11 + m] = add2(pk2(hadd2(a1[2 * m]), hadd2(a1[2 * m + 1])), bp);
            }
        }
        __syncwarp();
        // 64 rows x 66 floats = 1056 float4, contiguous in gmem
        const float4* rb = (const float4*)wbase;
        float4* ob = (float4*)(out + (size_t)((i << 10) + jb) * 66ull);
#pragma unroll 4
        for (int e = lane; e < 1056; e += 32) ob[e] = rb[e];
    }
}

extern "C" void kernel_launch(void* const* d_in, const int* in_sizes, int n_in,
                              void* d_out, int out_size) {
    const float* pc   = (const float*)d_in[0];
    const float* nrm  = (const float*)d_in[1];
    const float* dist = (const float*)d_in[2];
    const float* feat = (const float*)d_in[3];
    const float* w0   = (const float*)d_in[4];   const float* b0   = (const float*)d_in[5];
    const float* w1   = (const float*)d_in[6];   const float* b1   = (const float*)d_in[7];
    const float* l0w2 = (const float*)d_in[8];   const float* l0b2 = (const float*)d_in[9];
    const float* l1w1 = (const float*)d_in[10];  const float* l1b1 = (const float*)d_in[11];
    const float* l1w2 = (const float*)d_in[12];  const float* l1b2 = (const float*)d_in[13];
    const float* l2w0 = (const float*)d_in[14];  const float* l2b0 = (const float*)d_in[15];
    const float* l2w1 = (const float*)d_in[16];  const float* l2b1 = (const float*)d_in[17];
    const float* l2w2 = (const float*)d_in[18];  const float* l2b2 = (const float*)d_in[19];
    const float* fw   = (const float*)d_in[20];  const float* fb   = (const float*)d_in[21];
    float* out = (float*)d_out;

    cudaFuncSetAttribute(ppf_main, cudaFuncAttributeMaxDynamicSharedMemorySize, SMEM_BYTES);

    ppf_pre<<<128, 256>>>(feat, w0, b0, w1, b1);
    ppf_main<<<2048, 256, SMEM_BYTES>>>(pc, nrm, dist, w0, w1,
                                        l0w2, l0b2, l1w1, l1b1, l1w2, l1b2,
                                        l2w0, l2b0, l2w1, l2b1, l2w2, l2b2,
                                        fw, fb, out);
}

// round 4
// speedup vs baseline: 3.1876x; 3.1876x over previous
#include <cuda_runtime.h>
#include <cuda_bf16.h>
#include <cstdint>

typedef unsigned long long u64;
typedef unsigned u32;

// ================= per-point separable layer0 precompute (fp32) =================
__device__ float g_A0[1024 * 32];   // feat@l0_fc0_w[0:40] + b0  (i part)
__device__ float g_B0[1024 * 32];   // feat@l0_fc0_w[40:80]      (j part)
__device__ float g_A1[1024 * 32];   // feat@l0_fc1_w[0:40] + b1
__device__ float g_B1[1024 * 32];

__global__ void ppf_pre(const float* __restrict__ feat,
                        const float* __restrict__ w0, const float* __restrict__ b0,
                        const float* __restrict__ w1, const float* __restrict__ b1) {
    int t = blockIdx.x * blockDim.x + threadIdx.x;   // 32768 threads
    int i = t >> 5, c = t & 31;
    const float* f = feat + i * 40;
    float a0 = b0[c], bo0 = 0.f, a1 = b1[c], bo1 = 0.f;
#pragma unroll 8
    for (int k = 0; k < 40; k++) {
        float fv = f[k];
        a0  = fmaf(fv, w0[k * 32 + c],        a0);
        bo0 = fmaf(fv, w0[(k + 40) * 32 + c], bo0);
        a1  = fmaf(fv, w1[k * 32 + c],        a1);
        bo1 = fmaf(fv, w1[(k + 40) * 32 + c], bo1);
    }
    g_A0[i * 32 + c] = a0;
    g_B0[i * 32 + c] = bo0;
    g_A1[i * 32 + c] = a1;
    g_B1[i * 32 + c] = bo1;
}

// ================= weight B-fragment prep (bf16 hi/lo) =================
// Tile = (ktile, ntile) of a K x N weight. Per tile: [2 pass(hi/lo)][32 lanes] u64,
// u64 = {b1,b0} where b0 = bf16x2 of W rows (2c, 2c+1), b1 = rows (2c+8, 2c+9), col = lane/4.
#define T_W1P   0    // 1kt x 4nt  (l0_fc1_w rows 80..83, zero-padded K=16)
#define T_W0P   4
#define T_L0W2  8    // 2kt x 4nt
#define T_L1W1  16
#define T_L1W2  24
#define T_L2W0  32   // 2kt x 2nt
#define T_L2W1  36
#define T_L2W2  40   // 1kt x 2nt
#define T_FW    42   // 1kt x 9nt (N=66 padded to 72)
#define N_TILES 51

__device__ u64 g_frag[N_TILES * 64];

__device__ __forceinline__ u32 bfb(float v) {
    u32 r; asm("cvt.rn.bf16x2.f32 %0, %1, %2;" : "=r"(r) : "f"(0.f), "f"(v));
    return r & 0xFFFFu;     // low half = bf16(v)
}
__device__ __forceinline__ float bf16f(float v) {
    return __uint_as_float(bfb(v) << 16);
}

__global__ void frag_prep(const float* __restrict__ fc0w, const float* __restrict__ fc1w,
                          const float* __restrict__ l0w2, const float* __restrict__ l1w1,
                          const float* __restrict__ l1w2, const float* __restrict__ l2w0,
                          const float* __restrict__ l2w1, const float* __restrict__ l2w2,
                          const float* __restrict__ fw) {
    struct Spec { const float* w; int K, N, nnt, base, ntiles; };
    Spec sp[9] = {
        {fc1w + 80 * 32, 4, 32, 4, T_W1P, 4},
        {fc0w + 80 * 32, 4, 32, 4, T_W0P, 4},
        {l0w2, 32, 32, 4, T_L0W2, 8},
        {l1w1, 32, 32, 4, T_L1W1, 8},
        {l1w2, 32, 32, 4, T_L1W2, 8},
        {l2w0, 32, 16, 2, T_L2W0, 4},
        {l2w1, 32, 16, 2, T_L2W1, 4},
        {l2w2, 16, 16, 2, T_L2W2, 2},
        {fw,   16, 66, 9, T_FW,   9},
    };
    for (int e = threadIdx.x; e < N_TILES * 64; e += blockDim.x) {
        int tile = e >> 6, rem = e & 63, pass = rem >> 5, lane = rem & 31;
        int si = 0;
        for (int q = 0; q < 9; q++)
            if (tile >= sp[q].base && tile < sp[q].base + sp[q].ntiles) si = q;
        const float* w = sp[si].w;
        int K = sp[si].K, N = sp[si].N, nnt = sp[si].nnt;
        int lt = tile - sp[si].base, kt = lt / nnt, nt = lt % nnt;
        int n = nt * 8 + (lane >> 2), cc = lane & 3;
        int ks[4] = {kt * 16 + 2 * cc, kt * 16 + 2 * cc + 1,
                     kt * 16 + 2 * cc + 8, kt * 16 + 2 * cc + 9};
        u32 bits[4];
#pragma unroll
        for (int q = 0; q < 4; q++) {
            int k = ks[q];
            float v = (k < K && n < N) ? w[k * N + n] : 0.f;
            if (pass == 1) v = v - bf16f(v);   // lo residue
            bits[q] = bfb(v);
        }
        u32 b0 = (bits[1] << 16) | bits[0];
        u32 b1 = (bits[3] << 16) | bits[2];
        g_frag[e] = ((u64)b1 << 32) | (u64)b0;
    }
}

// ================= MMA helpers =================
__device__ __forceinline__ void mma_acc(float c[4], const u32 a[4], u64 b) {
    u32 b0 = (u32)b, b1 = (u32)(b >> 32);
    asm volatile("mma.sync.aligned.m16n8k16.row.col.f32.bf16.bf16.f32 "
        "{%0,%1,%2,%3}, {%4,%5,%6,%7}, {%8,%9}, {%0,%1,%2,%3};"
        : "+f"(c[0]), "+f"(c[1]), "+f"(c[2]), "+f"(c[3])
        : "r"(a[0]), "r"(a[1]), "r"(a[2]), "r"(a[3]), "r"(b0), "r"(b1));
}

// pack (x0 -> low, x1 -> high) into bf16x2 hi, residue into lo
__device__ __forceinline__ void split2(float x0, float x1, u32& hi, u32& lo) {
    u32 h;
    asm("cvt.rn.bf16x2.f32 %0, %1, %2;" : "=r"(h) : "f"(x1), "f"(x0));
    float r0 = x0 - __uint_as_float(h << 16);
    float r1 = x1 - __uint_as_float(h & 0xFFFF0000u);
    u32 l;
    asm("cvt.rn.bf16x2.f32 %0, %1, %2;" : "=r"(l) : "f"(r1), "f"(r0));
    hi = h; lo = l;
}

// D tiles (ntile 2kt, 2kt+1) -> A frag (ktile kt) with optional relu
template<bool RELU>
__device__ __forceinline__ void d2a(const float* d0, const float* d1, u32* ah, u32* al) {
    float v0 = d0[0], v1 = d0[1], v2 = d0[2], v3 = d0[3];
    float w0 = d1[0], w1 = d1[1], w2 = d1[2], w3 = d1[3];
    if (RELU) {
        v0 = fmaxf(v0, 0.f); v1 = fmaxf(v1, 0.f); v2 = fmaxf(v2, 0.f); v3 = fmaxf(v3, 0.f);
        w0 = fmaxf(w0, 0.f); w1 = fmaxf(w1, 0.f); w2 = fmaxf(w2, 0.f); w3 = fmaxf(w3, 0.f);
    }
    split2(v0, v1, ah[0], al[0]);
    split2(v2, v3, ah[1], al[1]);
    split2(w0, w1, ah[2], al[2]);
    split2(w2, w3, ah[3], al[3]);
}

// 3-pass bf16x3 mma into c
__device__ __forceinline__ void mma3(float c[4], const u32 ah[4], const u32 al[4],
                                     u64 wh, u64 wl) {
    mma_acc(c, ah, wh);
    mma_acc(c, ah, wl);
    mma_acc(c, al, wh);
}

// ================= main kernel: warp = 32 pairs (2 m16 tiles) =================
__global__ void __launch_bounds__(128) ppf_main(
    const float* __restrict__ pc, const float* __restrict__ nrm,
    const float* __restrict__ dist,
    const float* __restrict__ l0b2, const float* __restrict__ l1b1,
    const float* __restrict__ l1b2, const float* __restrict__ l2b0,
    const float* __restrict__ l2b1, const float* __restrict__ l2b2,
    const float* __restrict__ fb, float* __restrict__ out)
{
    __shared__ float sppf[4][32][4];
    const int lane = threadIdx.x & 31, warp = threadIdx.x >> 5;
    const int bx = blockIdx.x;
    const int i = bx >> 3;
    const int jb = ((bx & 7) << 7) + (warp << 5);
    const int r = lane >> 2, cc = lane & 3;
    const int col0 = 2 * cc;

    // ---- PPF features: lane computes pair (i, jb+lane) ----
    {
        int j = jb + lane;
        float pcix = pc[3 * i], pciy = pc[3 * i + 1], pciz = pc[3 * i + 2];
        float nix = nrm[3 * i], niy = nrm[3 * i + 1], niz = nrm[3 * i + 2];
        float pcjx = pc[3 * j], pcjy = pc[3 * j + 1], pcjz = pc[3 * j + 2];
        float njx = nrm[3 * j], njy = nrm[3 * j + 1], njz = nrm[3 * j + 2];
        float dd = dist[(i << 10) + j];
        float inv = 1.0f / (dd + 1e-7f);
        float xx0 = pcix - pcjx, xx1 = pciy - pcjy, xx2 = pciz - pcjz;
        sppf[warp][lane][0] = (nix * xx0 + niy * xx1 + niz * xx2) * inv;
        sppf[warp][lane][1] = (njx * xx0 + njy * xx1 + njz * xx2) * inv;
        sppf[warp][lane][2] = nix * njx + niy * njy + niz * njz;
        sppf[warp][lane][3] = dd;
    }
    __syncwarp();

    // ---- ppf A-frags (single k16 tile; cols 4..15 zero) ----
    u32 pph[2][4], ppl[2][4];
#pragma unroll
    for (int mt = 0; mt < 2; mt++) {
        int r0 = 16 * mt + r;
        float x0 = 0.f, x1 = 0.f, y0 = 0.f, y1 = 0.f;
        if (cc < 2) {
            x0 = sppf[warp][r0][2 * cc];     x1 = sppf[warp][r0][2 * cc + 1];
            y0 = sppf[warp][r0 + 8][2 * cc]; y1 = sppf[warp][r0 + 8][2 * cc + 1];
        }
        split2(x0, x1, pph[mt][0], ppl[mt][0]);
        split2(y0, y1, pph[mt][1], ppl[mt][1]);
        pph[mt][2] = ppl[mt][2] = pph[mt][3] = ppl[mt][3] = 0u;
    }

    // ---- layer0: X1 = relu(A1[i] + B1[j] + ppf@W1p) ----
    float cx[2][4][4];
#pragma unroll
    for (int nt = 0; nt < 4; nt++) {
        int col = 8 * nt + col0;
        float2 av = *(const float2*)(g_A1 + (i << 5) + col);
#pragma unroll
        for (int mt = 0; mt < 2; mt++) {
            int j0 = jb + 16 * mt + r;
            float2 ba = *(const float2*)(g_B1 + (j0 << 5) + col);
            float2 bb = *(const float2*)(g_B1 + ((j0 + 8) << 5) + col);
            cx[mt][nt][0] = av.x + ba.x; cx[mt][nt][1] = av.y + ba.y;
            cx[mt][nt][2] = av.x + bb.x; cx[mt][nt][3] = av.y + bb.y;
        }
    }
#pragma unroll
    for (int nt = 0; nt < 4; nt++) {
        u64 wh = g_frag[(T_W1P + nt) * 64 + lane];
        u64 wl = g_frag[(T_W1P + nt) * 64 + 32 + lane];
#pragma unroll
        for (int mt = 0; mt < 2; mt++) mma3(cx[mt][nt], pph[mt], ppl[mt], wh, wl);
    }
    u32 x1h[2][2][4], x1l[2][2][4];
#pragma unroll
    for (int mt = 0; mt < 2; mt++)
#pragma unroll
        for (int kt = 0; kt < 2; kt++)
            d2a<true>(cx[mt][2 * kt], cx[mt][2 * kt + 1], x1h[mt][kt], x1l[mt][kt]);

    // ---- residual R0 = A0[i] + B0[j] + ppf@W0p  (reuse cx) ----
#pragma unroll
    for (int nt = 0; nt < 4; nt++) {
        int col = 8 * nt + col0;
        float2 av = *(const float2*)(g_A0 + (i << 5) + col);
#pragma unroll
        for (int mt = 0; mt < 2; mt++) {
            int j0 = jb + 16 * mt + r;
            float2 ba = *(const float2*)(g_B0 + (j0 << 5) + col);
            float2 bb = *(const float2*)(g_B0 + ((j0 + 8) << 5) + col);
            cx[mt][nt][0] = av.x + ba.x; cx[mt][nt][1] = av.y + ba.y;
            cx[mt][nt][2] = av.x + bb.x; cx[mt][nt][3] = av.y + bb.y;
        }
    }
#pragma unroll
    for (int nt = 0; nt < 4; nt++) {
        u64 wh = g_frag[(T_W0P + nt) * 64 + lane];
        u64 wl = g_frag[(T_W0P + nt) * 64 + 32 + lane];
#pragma unroll
        for (int mt = 0; mt < 2; mt++) mma3(cx[mt][nt], pph[mt], ppl[mt], wh, wl);
    }

    // ---- l0fc2: X2 = X1@W2 + b2 + R0  (accumulate on top of R0) ----
#pragma unroll
    for (int nt = 0; nt < 4; nt++) {
        float2 bv = *(const float2*)(l0b2 + 8 * nt + col0);
#pragma unroll
        for (int mt = 0; mt < 2; mt++) {
            cx[mt][nt][0] += bv.x; cx[mt][nt][1] += bv.y;
            cx[mt][nt][2] += bv.x; cx[mt][nt][3] += bv.y;
        }
    }
#pragma unroll
    for (int kt = 0; kt < 2; kt++)
#pragma unroll
        for (int nt = 0; nt < 4; nt++) {
            u64 wh = g_frag[(T_L0W2 + kt * 4 + nt) * 64 + lane];
            u64 wl = g_frag[(T_L0W2 + kt * 4 + nt) * 64 + 32 + lane];
#pragma unroll
            for (int mt = 0; mt < 2; mt++) mma3(cx[mt][nt], x1h[mt][kt], x1l[mt][kt], wh, wl);
        }
    // cx = X2
    u32 x2h[2][2][4], x2l[2][2][4];
#pragma unroll
    for (int mt = 0; mt < 2; mt++)
#pragma unroll
        for (int kt = 0; kt < 2; kt++)
            d2a<false>(cx[mt][2 * kt], cx[mt][2 * kt + 1], x2h[mt][kt], x2l[mt][kt]);

    // ---- layer1 fc1: H = relu(X2@W1 + b1) ----
    float ch[2][4][4];
#pragma unroll
    for (int nt = 0; nt < 4; nt++) {
        float2 bv = *(const float2*)(l1b1 + 8 * nt + col0);
#pragma unroll
        for (int mt = 0; mt < 2; mt++) {
            ch[mt][nt][0] = bv.x; ch[mt][nt][1] = bv.y;
            ch[mt][nt][2] = bv.x; ch[mt][nt][3] = bv.y;
        }
    }
#pragma unroll
    for (int kt = 0; kt < 2; kt++)
#pragma unroll
        for (int nt = 0; nt < 4; nt++) {
            u64 wh = g_frag[(T_L1W1 + kt * 4 + nt) * 64 + lane];
            u64 wl = g_frag[(T_L1W1 + kt * 4 + nt) * 64 + 32 + lane];
#pragma unroll
            for (int mt = 0; mt < 2; mt++) mma3(ch[mt][nt], x2h[mt][kt], x2l[mt][kt], wh, wl);
        }
    u32 hh[2][2][4], hl[2][2][4];
#pragma unroll
    for (int mt = 0; mt < 2; mt++)
#pragma unroll
        for (int kt = 0; kt < 2; kt++)
            d2a<true>(ch[mt][2 * kt], ch[mt][2 * kt + 1], hh[mt][kt], hl[mt][kt]);

    // ---- layer1 fc2: X3 = H@W2 + b2 + X2  (accumulate onto cx which holds X2) ----
#pragma unroll
    for (int nt = 0; nt < 4; nt++) {
        float2 bv = *(const float2*)(l1b2 + 8 * nt + col0);
#pragma unroll
        for (int mt = 0; mt < 2; mt++) {
            cx[mt][nt][0] += bv.x; cx[mt][nt][1] += bv.y;
            cx[mt][nt][2] += bv.x; cx[mt][nt][3] += bv.y;
        }
    }
#pragma unroll
    for (int kt = 0; kt < 2; kt++)
#pragma unroll
        for (int nt = 0; nt < 4; nt++) {
            u64 wh = g_frag[(T_L1W2 + kt * 4 + nt) * 64 + lane];
            u64 wl = g_frag[(T_L1W2 + kt * 4 + nt) * 64 + 32 + lane];
#pragma unroll
            for (int mt = 0; mt < 2; mt++) mma3(cx[mt][nt], hh[mt][kt], hl[mt][kt], wh, wl);
        }
    // cx = X3
    u32 x3h[2][2][4], x3l[2][2][4];
#pragma unroll
    for (int mt = 0; mt < 2; mt++)
#pragma unroll
        for (int kt = 0; kt < 2; kt++)
            d2a<false>(cx[mt][2 * kt], cx[mt][2 * kt + 1], x3h[mt][kt], x3l[mt][kt]);

    // ---- layer2: R2 = X3@fc0 + b0 ; H2 = relu(X3@fc1 + b1) ; X4 = H2@fc2 + b2 + R2 ----
    float ca[2][2][4], cb[2][2][4];
#pragma unroll
    for (int nt = 0; nt < 2; nt++) {
        float2 b0v = *(const float2*)(l2b0 + 8 * nt + col0);
        float2 b1v = *(const float2*)(l2b1 + 8 * nt + col0);
#pragma unroll
        for (int mt = 0; mt < 2; mt++) {
            ca[mt][nt][0] = b0v.x; ca[mt][nt][1] = b0v.y;
            ca[mt][nt][2] = b0v.x; ca[mt][nt][3] = b0v.y;
            cb[mt][nt][0] = b1v.x; cb[mt][nt][1] = b1v.y;
            cb[mt][nt][2] = b1v.x; cb[mt][nt][3] = b1v.y;
        }
    }
#pragma unroll
    for (int kt = 0; kt < 2; kt++)
#pragma unroll
        for (int nt = 0; nt < 2; nt++) {
            u64 w0h = g_frag[(T_L2W0 + kt * 2 + nt) * 64 + lane];
            u64 w0l = g_frag[(T_L2W0 + kt * 2 + nt) * 64 + 32 + lane];
            u64 w1h = g_frag[(T_L2W1 + kt * 2 + nt) * 64 + lane];
            u64 w1l = g_frag[(T_L2W1 + kt * 2 + nt) * 64 + 32 + lane];
#pragma unroll
            for (int mt = 0; mt < 2; mt++) {
                mma3(ca[mt][nt], x3h[mt][kt], x3l[mt][kt], w0h, w0l);
                mma3(cb[mt][nt], x3h[mt][kt], x3l[mt][kt], w1h, w1l);
            }
        }
    u32 h2h[2][4], h2l[2][4];
#pragma unroll
    for (int mt = 0; mt < 2; mt++) d2a<true>(cb[mt][0], cb[mt][1], h2h[mt], h2l[mt]);
    // X4 accumulates onto ca (=R2) + b2
#pragma unroll
    for (int nt = 0; nt < 2; nt++) {
        float2 bv = *(const float2*)(l2b2 + 8 * nt + col0);
#pragma unroll
        for (int mt = 0; mt < 2; mt++) {
            ca[mt][nt][0] += bv.x; ca[mt][nt][1] += bv.y;
            ca[mt][nt][2] += bv.x; ca[mt][nt][3] += bv.y;
        }
        u64 wh = g_frag[(T_L2W2 + nt) * 64 + lane];
        u64 wl = g_frag[(T_L2W2 + nt) * 64 + 32 + lane];
#pragma unroll
        for (int mt = 0; mt < 2; mt++) mma3(ca[mt][nt], h2h[mt], h2l[mt], wh, wl);
    }
    u32 x4h[2][4], x4l[2][4];
#pragma unroll
    for (int mt = 0; mt < 2; mt++) d2a<false>(ca[mt][0], ca[mt][1], x4h[mt], x4l[mt]);

    // ---- final: OUT = X4 @ fw + fb  (N=66, 9 n-tiles, direct STG.64) ----
#pragma unroll
    for (int nt = 0; nt < 9; nt++) {
        int col = 8 * nt + col0;
        bool valid = (col < 66);
        float2 bv = valid ? *(const float2*)(fb + col) : make_float2(0.f, 0.f);
        u64 wh = g_frag[(T_FW + nt) * 64 + lane];
        u64 wl = g_frag[(T_FW + nt) * 64 + 32 + lane];
#pragma unroll
        for (int mt = 0; mt < 2; mt++) {
            float cf[4] = {bv.x, bv.y, bv.x, bv.y};
            mma3(cf, x4h[mt], x4l[mt], wh, wl);
            if (valid) {
                int j0 = jb + 16 * mt + r;
                size_t base = (size_t)((i << 10) + j0) * 66ull + col;
                *(float2*)(out + base) = make_float2(cf[0], cf[1]);
                *(float2*)(out + base + 8ull * 66ull) = make_float2(cf[2], cf[3]);
            }
        }
    }
}

extern "C" void kernel_launch(void* const* d_in, const int* in_sizes, int n_in,
                              void* d_out, int out_size) {
    const float* pc   = (const float*)d_in[0];
    const float* nrm  = (const float*)d_in[1];
    const float* dist = (const float*)d_in[2];
    const float* feat = (const float*)d_in[3];
    const float* w0   = (const float*)d_in[4];   const float* b0   = (const float*)d_in[5];
    const float* w1   = (const float*)d_in[6];   const float* b1   = (const float*)d_in[7];
    const float* l0w2 = (const float*)d_in[8];   const float* l0b2 = (const float*)d_in[9];
    const float* l1w1 = (const float*)d_in[10];  const float* l1b1 = (const float*)d_in[11];
    const float* l1w2 = (const float*)d_in[12];  const float* l1b2 = (const float*)d_in[13];
    const float* l2w0 = (const float*)d_in[14];  const float* l2b0 = (const float*)d_in[15];
    const float* l2w1 = (const float*)d_in[16];  const float* l2b1 = (const float*)d_in[17];
    const float* l2w2 = (const float*)d_in[18];  const float* l2b2 = (const float*)d_in[19];
    const float* fw   = (const float*)d_in[20];  const float* fb   = (const float*)d_in[21];
    float* out = (float*)d_out;

    ppf_pre<<<128, 256>>>(feat, w0, b0, w1, b1);
    frag_prep<<<1, 256>>>(w0, w1, l0w2, l1w1, l1w2, l2w0, l2w1, l2w2, fw);
    ppf_main<<<8192, 128>>>(pc, nrm, dist,
                            l0b2, l1b1, l1b2, l2b0, l2b1, l2b2, fb, out);
}

// round 5
// speedup vs baseline: 3.6130x; 1.1334x over previous
#include <cuda_runtime.h>
#include <cuda_fp16.h>
#include <cstdint>

typedef unsigned long long u64;
typedef unsigned u32;

// ================= per-point separable layer0 precompute (fp32) =================
__device__ float g_A0[1024 * 32];   // feat@l0_fc0_w[0:40] + b0  (i part)
__device__ float g_B0[1024 * 32];   // feat@l0_fc0_w[40:80]      (j part)
__device__ float g_A1[1024 * 32];   // feat@l0_fc1_w[0:40] + b1
__device__ float g_B1[1024 * 32];

// ================= weight B-fragments (single fp16) =================
// Tile (kt,nt): 32 u64 (one per lane). u64 = {b1,b0}; b0 = fp16x2 of W rows (2c,2c+1),
// b1 = rows (2c+8,2c+9), col = 8*nt + lane/4.
#define T_L0W2  0    // 2kt x 4nt
#define T_L1W1  8
#define T_L1W2  16
#define T_L2W0  24   // 2kt x 2nt
#define T_L2W1  28
#define T_L2W2  32   // 1kt x 2nt
#define T_FW    34   // 1kt x 9nt (N=66 pad 72)
#define N_TILES 43

__device__ u64 g_frag[N_TILES * 32];

__device__ __forceinline__ u32 h16b(float v) {
    return (u32)__half_as_ushort(__float2half_rn(v));
}

// ---- fused prep: blocks [0,256) = per-point tables; blocks [256,267) = frags ----
__global__ void prep(const float* __restrict__ feat,
                     const float* __restrict__ w0, const float* __restrict__ b0,
                     const float* __restrict__ w1, const float* __restrict__ b1,
                     const float* __restrict__ l0w2, const float* __restrict__ l1w1,
                     const float* __restrict__ l1w2, const float* __restrict__ l2w0,
                     const float* __restrict__ l2w1, const float* __restrict__ l2w2,
                     const float* __restrict__ fw) {
    int b = blockIdx.x;
    if (b < 256) {
        int t = b * 256 + threadIdx.x;          // 65536 threads
        int i = t >> 6, rem = t & 63, sel = rem >> 5, c = rem & 31;
        const float* f = feat + i * 40;
        const float* w = sel ? w1 : w0;
        float a = sel ? b1[c] : b0[c], bo = 0.f;
#pragma unroll 8
        for (int k = 0; k < 40; k++) {
            float fv = f[k];
            a  = fmaf(fv, w[k * 32 + c],        a);
            bo = fmaf(fv, w[(k + 40) * 32 + c], bo);
        }
        if (sel) { g_A1[i * 32 + c] = a; g_B1[i * 32 + c] = bo; }
        else     { g_A0[i * 32 + c] = a; g_B0[i * 32 + c] = bo; }
    } else {
        int e = (b - 256) * 256 + threadIdx.x;
        if (e >= N_TILES * 32) return;
        struct Spec { const float* w; int K, N, nnt, base, ntiles; };
        Spec sp[7] = {
            {l0w2, 32, 32, 4, T_L0W2, 8},
            {l1w1, 32, 32, 4, T_L1W1, 8},
            {l1w2, 32, 32, 4, T_L1W2, 8},
            {l2w0, 32, 16, 2, T_L2W0, 4},
            {l2w1, 32, 16, 2, T_L2W1, 4},
            {l2w2, 16, 16, 2, T_L2W2, 2},
            {fw,   16, 66, 9, T_FW,   9},
        };
        int tile = e >> 5, lane = e & 31;
        int si = 0;
        for (int q = 0; q < 7; q++)
            if (tile >= sp[q].base && tile < sp[q].base + sp[q].ntiles) si = q;
        const float* w = sp[si].w;
        int K = sp[si].K, N = sp[si].N, nnt = sp[si].nnt;
        int lt = tile - sp[si].base, kt = lt / nnt, nt = lt % nnt;
        int n = nt * 8 + (lane >> 2), cc = lane & 3;
        int ks[4] = {kt * 16 + 2 * cc, kt * 16 + 2 * cc + 1,
                     kt * 16 + 2 * cc + 8, kt * 16 + 2 * cc + 9};
        u32 bits[4];
#pragma unroll
        for (int q = 0; q < 4; q++) {
            int k = ks[q];
            float v = (k < K && n < N) ? w[k * N + n] : 0.f;
            bits[q] = h16b(v);
        }
        u32 lo = (bits[1] << 16) | bits[0];
        u32 hi = (bits[3] << 16) | bits[2];
        g_frag[e] = ((u64)hi << 32) | (u64)lo;
    }
}

// ================= MMA helpers (fp16 in, fp32 acc) =================
__device__ __forceinline__ void mma_acc(float c[4], const u32 a[4], u64 b) {
    u32 b0 = (u32)b, b1 = (u32)(b >> 32);
    asm volatile("mma.sync.aligned.m16n8k16.row.col.f32.f16.f16.f32 "
        "{%0,%1,%2,%3}, {%4,%5,%6,%7}, {%8,%9}, {%0,%1,%2,%3};"
        : "+f"(c[0]), "+f"(c[1]), "+f"(c[2]), "+f"(c[3])
        : "r"(a[0]), "r"(a[1]), "r"(a[2]), "r"(a[3]), "r"(b0), "r"(b1));
}
__device__ __forceinline__ void mma2(float c[4], const u32 ah[4], const u32 al[4], u64 w) {
    mma_acc(c, ah, w);
    mma_acc(c, al, w);
}

// pack (x0 low, x1 high) into fp16x2 hi, residue into lo
__device__ __forceinline__ void split2(float x0, float x1, u32& hi, u32& lo) {
    __half2 h = __floats2half2_rn(x0, x1);
    float2 f = __half22float2(h);
    __half2 l = __floats2half2_rn(x0 - f.x, x1 - f.y);
    hi = *reinterpret_cast<u32*>(&h);
    lo = *reinterpret_cast<u32*>(&l);
}

// D tiles (ntile 2kt, 2kt+1) -> A frag (ktile kt), optional relu
template<bool RELU>
__device__ __forceinline__ void d2a(const float* d0, const float* d1, u32* ah, u32* al) {
    float v0 = d0[0], v1 = d0[1], v2 = d0[2], v3 = d0[3];
    float w0 = d1[0], w1 = d1[1], w2 = d1[2], w3 = d1[3];
    if (RELU) {
        v0 = fmaxf(v0, 0.f); v1 = fmaxf(v1, 0.f); v2 = fmaxf(v2, 0.f); v3 = fmaxf(v3, 0.f);
        w0 = fmaxf(w0, 0.f); w1 = fmaxf(w1, 0.f); w2 = fmaxf(w2, 0.f); w3 = fmaxf(w3, 0.f);
    }
    split2(v0, v1, ah[0], al[0]);
    split2(v2, v3, ah[1], al[1]);
    split2(w0, w1, ah[2], al[2]);
    split2(w2, w3, ah[3], al[3]);
}

// ================= main kernel: warp = 32 pairs (2 m16 tiles) =================
__global__ void __launch_bounds__(128) ppf_main(
    const float* __restrict__ pc, const float* __restrict__ nrm,
    const float* __restrict__ dist,
    const float* __restrict__ fc0w, const float* __restrict__ fc1w,
    const float* __restrict__ l0b2, const float* __restrict__ l1b1,
    const float* __restrict__ l1b2, const float* __restrict__ l2b0,
    const float* __restrict__ l2b1, const float* __restrict__ l2b2,
    const float* __restrict__ fb, float* __restrict__ out)
{
    __shared__ float sppf[4][32][4];
    __shared__ float sW1p[4][32];
    __shared__ float sW0p[4][32];
    const int tid = threadIdx.x;
    const int lane = tid & 31, warp = tid >> 5;
    const int bx = blockIdx.x;
    const int i = bx >> 3;
    const int jb = ((bx & 7) << 7) + (warp << 5);
    const int r = lane >> 2, cc = lane & 3;
    const int col0 = 2 * cc;

    // stage ppf-weight rows (80..83) of fc1/fc0
    if (tid < 128) {
        sW1p[tid >> 5][tid & 31] = fc1w[80 * 32 + tid];
        sW0p[tid >> 5][tid & 31] = fc0w[80 * 32 + tid];
    }

    // ---- PPF features: lane computes pair (i, jb+lane) ----
    {
        int j = jb + lane;
        float pcix = pc[3 * i], pciy = pc[3 * i + 1], pciz = pc[3 * i + 2];
        float nix = nrm[3 * i], niy = nrm[3 * i + 1], niz = nrm[3 * i + 2];
        float pcjx = pc[3 * j], pcjy = pc[3 * j + 1], pcjz = pc[3 * j + 2];
        float njx = nrm[3 * j], njy = nrm[3 * j + 1], njz = nrm[3 * j + 2];
        float dd = dist[(i << 10) + j];
        float inv = 1.0f / (dd + 1e-7f);
        float xx0 = pcix - pcjx, xx1 = pciy - pcjy, xx2 = pciz - pcjz;
        sppf[warp][lane][0] = (nix * xx0 + niy * xx1 + niz * xx2) * inv;
        sppf[warp][lane][1] = (njx * xx0 + njy * xx1 + njz * xx2) * inv;
        sppf[warp][lane][2] = nix * njx + niy * njy + niz * njz;
        sppf[warp][lane][3] = dd;
    }
    __syncthreads();

    // ppf rows this lane needs (fp32, exact)
    float pA[2][4], pB[2][4];
#pragma unroll
    for (int mt = 0; mt < 2; mt++) {
        int lr = 16 * mt + r;
#pragma unroll
        for (int k = 0; k < 4; k++) {
            pA[mt][k] = sppf[warp][lr][k];
            pB[mt][k] = sppf[warp][lr + 8][k];
        }
    }

    // ---- layer0: X1 = relu(A1[i] + B1[j] + ppf@W1p)  (scalar fp32 ppf GEMM) ----
    float cx[2][4][4];
#pragma unroll
    for (int nt = 0; nt < 4; nt++) {
        int col = 8 * nt + col0;
        float2 av = *(const float2*)(g_A1 + (i << 5) + col);
#pragma unroll
        for (int mt = 0; mt < 2; mt++) {
            int j0 = jb + 16 * mt + r;
            float2 ba = *(const float2*)(g_B1 + (j0 << 5) + col);
            float2 bb = *(const float2*)(g_B1 + ((j0 + 8) << 5) + col);
            float c0 = av.x + ba.x, c1 = av.y + ba.y;
            float c2 = av.x + bb.x, c3 = av.y + bb.y;
#pragma unroll
            for (int k = 0; k < 4; k++) {
                float2 wv = *(const float2*)&sW1p[k][col];
                c0 = fmaf(pA[mt][k], wv.x, c0); c1 = fmaf(pA[mt][k], wv.y, c1);
                c2 = fmaf(pB[mt][k], wv.x, c2); c3 = fmaf(pB[mt][k], wv.y, c3);
            }
            cx[mt][nt][0] = c0; cx[mt][nt][1] = c1; cx[mt][nt][2] = c2; cx[mt][nt][3] = c3;
        }
    }
    u32 x1h[2][2][4], x1l[2][2][4];
#pragma unroll
    for (int mt = 0; mt < 2; mt++)
#pragma unroll
        for (int kt = 0; kt < 2; kt++)
            d2a<true>(cx[mt][2 * kt], cx[mt][2 * kt + 1], x1h[mt][kt], x1l[mt][kt]);

    // ---- residual R0 = A0[i] + B0[j] + ppf@W0p  (reuse cx) ----
#pragma unroll
    for (int nt = 0; nt < 4; nt++) {
        int col = 8 * nt + col0;
        float2 av = *(const float2*)(g_A0 + (i << 5) + col);
#pragma unroll
        for (int mt = 0; mt < 2; mt++) {
            int j0 = jb + 16 * mt + r;
            float2 ba = *(const float2*)(g_B0 + (j0 << 5) + col);
            float2 bb = *(const float2*)(g_B0 + ((j0 + 8) << 5) + col);
            float c0 = av.x + ba.x, c1 = av.y + ba.y;
            float c2 = av.x + bb.x, c3 = av.y + bb.y;
#pragma unroll
            for (int k = 0; k < 4; k++) {
                float2 wv = *(const float2*)&sW0p[k][col];
                c0 = fmaf(pA[mt][k], wv.x, c0); c1 = fmaf(pA[mt][k], wv.y, c1);
                c2 = fmaf(pB[mt][k], wv.x, c2); c3 = fmaf(pB[mt][k], wv.y, c3);
            }
            cx[mt][nt][0] = c0; cx[mt][nt][1] = c1; cx[mt][nt][2] = c2; cx[mt][nt][3] = c3;
        }
    }

    // ---- l0fc2: X2 = X1@W2 + b2 + R0 ----
#pragma unroll
    for (int nt = 0; nt < 4; nt++) {
        float2 bv = *(const float2*)(l0b2 + 8 * nt + col0);
#pragma unroll
        for (int mt = 0; mt < 2; mt++) {
            cx[mt][nt][0] += bv.x; cx[mt][nt][1] += bv.y;
            cx[mt][nt][2] += bv.x; cx[mt][nt][3] += bv.y;
        }
    }
#pragma unroll
    for (int kt = 0; kt < 2; kt++)
#pragma unroll
        for (int nt = 0; nt < 4; nt++) {
            u64 wv = g_frag[(T_L0W2 + kt * 4 + nt) * 32 + lane];
#pragma unroll
            for (int mt = 0; mt < 2; mt++) mma2(cx[mt][nt], x1h[mt][kt], x1l[mt][kt], wv);
        }
    u32 x2h[2][2][4], x2l[2][2][4];
#pragma unroll
    for (int mt = 0; mt < 2; mt++)
#pragma unroll
        for (int kt = 0; kt < 2; kt++)
            d2a<false>(cx[mt][2 * kt], cx[mt][2 * kt + 1], x2h[mt][kt], x2l[mt][kt]);

    // ---- layer1 fc1: H = relu(X2@W1 + b1) ----
    float ch[2][4][4];
#pragma unroll
    for (int nt = 0; nt < 4; nt++) {
        float2 bv = *(const float2*)(l1b1 + 8 * nt + col0);
#pragma unroll
        for (int mt = 0; mt < 2; mt++) {
            ch[mt][nt][0] = bv.x; ch[mt][nt][1] = bv.y;
            ch[mt][nt][2] = bv.x; ch[mt][nt][3] = bv.y;
        }
    }
#pragma unroll
    for (int kt = 0; kt < 2; kt++)
#pragma unroll
        for (int nt = 0; nt < 4; nt++) {
            u64 wv = g_frag[(T_L1W1 + kt * 4 + nt) * 32 + lane];
#pragma unroll
            for (int mt = 0; mt < 2; mt++) mma2(ch[mt][nt], x2h[mt][kt], x2l[mt][kt], wv);
        }
    u32 hh[2][2][4], hl[2][2][4];
#pragma unroll
    for (int mt = 0; mt < 2; mt++)
#pragma unroll
        for (int kt = 0; kt < 2; kt++)
            d2a<true>(ch[mt][2 * kt], ch[mt][2 * kt + 1], hh[mt][kt], hl[mt][kt]);

    // ---- layer1 fc2: X3 = H@W2 + b2 + X2 (accumulate onto cx = X2) ----
#pragma unroll
    for (int nt = 0; nt < 4; nt++) {
        float2 bv = *(const float2*)(l1b2 + 8 * nt + col0);
#pragma unroll
        for (int mt = 0; mt < 2; mt++) {
            cx[mt][nt][0] += bv.x; cx[mt][nt][1] += bv.y;
            cx[mt][nt][2] += bv.x; cx[mt][nt][3] += bv.y;
        }
    }
#pragma unroll
    for (int kt = 0; kt < 2; kt++)
#pragma unroll
        for (int nt = 0; nt < 4; nt++) {
            u64 wv = g_frag[(T_L1W2 + kt * 4 + nt) * 32 + lane];
#pragma unroll
            for (int mt = 0; mt < 2; mt++) mma2(cx[mt][nt], hh[mt][kt], hl[mt][kt], wv);
        }
    u32 x3h[2][2][4], x3l[2][2][4];
#pragma unroll
    for (int mt = 0; mt < 2; mt++)
#pragma unroll
        for (int kt = 0; kt < 2; kt++)
            d2a<false>(cx[mt][2 * kt], cx[mt][2 * kt + 1], x3h[mt][kt], x3l[mt][kt]);

    // ---- layer2 ----
    float ca[2][2][4], cb[2][2][4];
#pragma unroll
    for (int nt = 0; nt < 2; nt++) {
        float2 b0v = *(const float2*)(l2b0 + 8 * nt + col0);
        float2 b1v = *(const float2*)(l2b1 + 8 * nt + col0);
#pragma unroll
        for (int mt = 0; mt < 2; mt++) {
            ca[mt][nt][0] = b0v.x; ca[mt][nt][1] = b0v.y;
            ca[mt][nt][2] = b0v.x; ca[mt][nt][3] = b0v.y;
            cb[mt][nt][0] = b1v.x; cb[mt][nt][1] = b1v.y;
            cb[mt][nt][2] = b1v.x; cb[mt][nt][3] = b1v.y;
        }
    }
#pragma unroll
    for (int kt = 0; kt < 2; kt++)
#pragma unroll
        for (int nt = 0; nt < 2; nt++) {
            u64 w0v = g_frag[(T_L2W0 + kt * 2 + nt) * 32 + lane];
            u64 w1v = g_frag[(T_L2W1 + kt * 2 + nt) * 32 + lane];
#pragma unroll
            for (int mt = 0; mt < 2; mt++) {
                mma2(ca[mt][nt], x3h[mt][kt], x3l[mt][kt], w0v);
                mma2(cb[mt][nt], x3h[mt][kt], x3l[mt][kt], w1v);
            }
        }
    u32 h2h[2][4], h2l[2][4];
#pragma unroll
    for (int mt = 0; mt < 2; mt++) d2a<true>(cb[mt][0], cb[mt][1], h2h[mt], h2l[mt]);
#pragma unroll
    for (int nt = 0; nt < 2; nt++) {
        float2 bv = *(const float2*)(l2b2 + 8 * nt + col0);
#pragma unroll
        for (int mt = 0; mt < 2; mt++) {
            ca[mt][nt][0] += bv.x; ca[mt][nt][1] += bv.y;
            ca[mt][nt][2] += bv.x; ca[mt][nt][3] += bv.y;
        }
        u64 wv = g_frag[(T_L2W2 + nt) * 32 + lane];
#pragma unroll
        for (int mt = 0; mt < 2; mt++) mma2(ca[mt][nt], h2h[mt], h2l[mt], wv);
    }
    u32 x4h[2][4], x4l[2][4];
#pragma unroll
    for (int mt = 0; mt < 2; mt++) d2a<false>(ca[mt][0], ca[mt][1], x4h[mt], x4l[mt]);

    // ---- final: OUT = X4 @ fw + fb  (N=66, 9 n-tiles, direct STG.64) ----
#pragma unroll
    for (int nt = 0; nt < 9; nt++) {
        int col = 8 * nt + col0;
        bool valid = (col < 66);
        float2 bv = valid ? *(const float2*)(fb + col) : make_float2(0.f, 0.f);
        u64 wv = g_frag[(T_FW + nt) * 32 + lane];
#pragma unroll
        for (int mt = 0; mt < 2; mt++) {
            float cf[4] = {bv.x, bv.y, bv.x, bv.y};
            mma2(cf, x4h[mt], x4l[mt], wv);
            if (valid) {
                int j0 = jb + 16 * mt + r;
                size_t base = (size_t)((i << 10) + j0) * 66ull + col;
                *(float2*)(out + base) = make_float2(cf[0], cf[1]);
                *(float2*)(out + base + 8ull * 66ull) = make_float2(cf[2], cf[3]);
            }
        }
    }
}

extern "C" void kernel_launch(void* const* d_in, const int* in_sizes, int n_in,
                              void* d_out, int out_size) {
    const float* pc   = (const float*)d_in[0];
    const float* nrm  = (const float*)d_in[1];
    const float* dist = (const float*)d_in[2];
    const float* feat = (const float*)d_in[3];
    const float* w0   = (const float*)d_in[4];   const float* b0   = (const float*)d_in[5];
    const float* w1   = (const float*)d_in[6];   const float* b1   = (const float*)d_in[7];
    const float* l0w2 = (const float*)d_in[8];   const float* l0b2 = (const float*)d_in[9];
    const float* l1w1 = (const float*)d_in[10];  const float* l1b1 = (const float*)d_in[11];
    const float* l1w2 = (const float*)d_in[12];  const float* l1b2 = (const float*)d_in[13];
    const float* l2w0 = (const float*)d_in[14];  const float* l2b0 = (const float*)d_in[15];
    const float* l2w1 = (const float*)d_in[16];  const float* l2b1 = (const float*)d_in[17];
    const float* l2w2 = (const float*)d_in[18];  const float* l2b2 = (const float*)d_in[19];
    const float* fw   = (const float*)d_in[20];  const float* fb   = (const float*)d_in[21];
    float* out = (float*)d_out;

    prep<<<267, 256>>>(feat, w0, b0, w1, b1,
                       l0w2, l1w1, l1w2, l2w0, l2w1, l2w2, fw);
    ppf_main<<<8192, 128>>>(pc, nrm, dist, w0, w1,
                            l0b2, l1b1, l1b2, l2b0, l2b1, l2b2, fb, out);
}